// round 5
// baseline (speedup 1.0000x reference)
#include <cuda_runtime.h>

#define G        64
#define IMGSZ    512
#define NTHREADS 256

__device__ __forceinline__ float ldimg(const float* __restrict__ img, int gy, int gx) {
    if ((unsigned)gy < IMGSZ && (unsigned)gx < IMGSZ)
        return __ldg(img + gy * IMGSZ + gx);
    return 0.0f;
}

// Select 4 consecutive floats starting at OFF from concat(a, b). OFF in [0,3].
template<int OFF>
__device__ __forceinline__ void pick(const float4& a, const float4& b,
                                     float& c0, float& c1, float& c2, float& c3) {
    if constexpr (OFF == 0) { c0 = a.x; c1 = a.y; c2 = a.z; c3 = a.w; }
    else if constexpr (OFF == 1) { c0 = a.y; c1 = a.z; c2 = a.w; c3 = b.x; }
    else if constexpr (OFF == 2) { c0 = a.z; c1 = a.w; c2 = b.x; c3 = b.y; }
    else                         { c0 = a.w; c1 = b.x; c2 = b.y; c3 = b.z; }
}

// S=4 chunk runner: chunk m = 4 floats; s = [1,3,5,7]/32, t = [7,5,3,1]/32 dots.
// out_d = s_d + t_{d+1}; NCH chunks -> NCH-1 outputs into dst[0..NCH-2].
// Reads p[0 .. NCH] (caller guarantees bounds).
template<int OFF, int NCH>
__device__ __forceinline__ void run4(const float4* __restrict__ p, float* __restrict__ dst) {
    constexpr float W0 = 1.f/32, W1 = 3.f/32, W2 = 5.f/32, W3 = 7.f/32;
    float4 a = __ldg(p);
    float sp = 0.f;
#pragma unroll
    for (int dm = 0; dm < NCH; dm++) {
        float4 b = __ldg(p + dm + 1);
        float c0, c1, c2, c3; pick<OFF>(a, b, c0, c1, c2, c3);
        float s = W0*c0 + W1*c1 + W2*c2 + W3*c3;
        float t = W3*c0 + W2*c1 + W1*c2 + W0*c3;
        if (dm > 0) dst[dm - 1] = sp + t;
        sp = s;
        a = b;
    }
}

// S=2 chunk runner: chunk m = 2 floats; s = [1,3]/8, t = [3,1]/8.
// Two chunks per float4 step. Reads p[0 .. (OFF+2*NCH+3)/4].
template<int OFF, int NCH>
__device__ __forceinline__ void run2(const float4* __restrict__ p, float* __restrict__ dst) {
    constexpr float V0 = 1.f/8, V1 = 3.f/8;
    constexpr int NP = (NCH + 1) / 2;
    float4 a = __ldg(p);
    float sp = 0.f;
#pragma unroll
    for (int d2 = 0; d2 < NP; d2++) {
        float4 b = __ldg(p + d2 + 1);
        float c0, c1, c2, c3; pick<OFF>(a, b, c0, c1, c2, c3);
        {   // chunk dm = 2*d2
            float s = V0*c0 + V1*c1;
            float t = V1*c0 + V0*c1;
            if (2*d2 > 0) dst[2*d2 - 1] = sp + t;
            sp = s;
        }
        if (2*d2 + 1 < NCH) {   // chunk dm = 2*d2+1
            float s = V0*c2 + V1*c3;
            float t = V1*c2 + V0*c3;
            dst[2*d2] = sp + t;
            sp = s;
        }
        a = b;
    }
}

// Scalar fallback for one horizontal output i: patch renorm + image zero-pad.
// Row gy is guaranteed inside the image (rowp valid).
template<int S>
__device__ __forceinline__ float scalar_out(const float* __restrict__ rowp, int bx, int i) {
    constexpr int PS = G * S, NT = 2 * S;
    float acc = 0.f, wsum = 0.f;
#pragma unroll
    for (int k = 0; k < NT; k++) {
        int j = S*i - S/2 + k;
        if ((unsigned)j < (unsigned)PS) {
            float w = (1.0f - fabsf((float)k - ((float)S - 0.5f)) / (float)S) / (float)S;
            wsum += w;
            int gx = bx + j;
            if ((unsigned)gx < IMGSZ) acc += w * __ldg(rowp + gx);
        }
    }
    return acc / wsum;
}

__device__ __forceinline__ float4 f4fma(float w, float4 v, float4 acc) {
    acc.x += w*v.x; acc.y += w*v.y; acc.z += w*v.z; acc.w += w*v.w; return acc;
}

#define RUN_SWITCH(FN, NCH, p, dst, off)                                   \
    switch (off) {                                                         \
        case 0:  FN<0, NCH>(p, dst); break;                                \
        case 1:  FN<1, NCH>(p, dst); break;                                \
        case 2:  FN<2, NCH>(p, dst); break;                                \
        default: FN<3, NCH>(p, dst); break;                                \
    }

// ---------------- S = 4 slice ----------------
template <int ROWS>
__device__ void ds4_slice(const float* __restrict__ img, float* __restrict__ o,
                          int by, int bx, int y0, float* __restrict__ tmp) {
    constexpr int PS = 256, LR = 4 * ROWS + 4;
    constexpr float W0=1.f/32, W1=3.f/32, W2=5.f/32, W3=7.f/32,
                    W4=7.f/32, W5=5.f/32, W6=3.f/32, W7=1.f/32;
    const float W[8] = {W0,W1,W2,W3,W4,W5,W6,W7};
    const int tid = threadIdx.x;
    const int rb  = 4 * y0 - 2;

    // ---- phase 1: horizontal. 8 threads/row, 8 outputs each ----
    for (int it = tid; it < LR * 8; it += NTHREADS) {
        int lr = it >> 3, q = it & 7;
        int r  = rb + lr;
        if ((unsigned)r >= (unsigned)PS) continue;
        int gy = by + r;
        float* drow = tmp + lr * G;
        int i0 = 8 * q;
        if ((unsigned)gy >= IMGSZ) {
#pragma unroll
            for (int k = 0; k < 8; k++) drow[i0 + k] = 0.f;
            continue;
        }
        const float* rowp = img + gy * IMGSZ;
        int istart = (q == 0) ? 1 : ((q == 7) ? 56 : i0);
        int g0 = bx + 4 * istart - 2;
        int base = g0 & ~3;
        int off  = g0 & 3;
        if (g0 >= 0 && base + 40 <= IMGSZ) {
            const float4* p = (const float4*)(rowp + base);
            float* dst = drow + istart;
            if (q == 0) {
                RUN_SWITCH(run4, 8, p, dst, off);        // outputs 1..7
                drow[0] = scalar_out<4>(rowp, bx, 0);
            } else if (q == 7) {
                RUN_SWITCH(run4, 8, p, dst, off);        // outputs 56..62
                drow[63] = scalar_out<4>(rowp, bx, 63);
            } else {
                RUN_SWITCH(run4, 9, p, dst, off);        // outputs i0..i0+7
            }
        } else {
#pragma unroll
            for (int k = 0; k < 8; k++) drow[i0 + k] = scalar_out<4>(rowp, bx, i0 + k);
        }
    }
    __syncthreads();

    // ---- phase 2: vertical, float4 per thread ----
    for (int it = tid; it < ROWS * 16; it += NTHREADS) {
        int y  = y0 + (it >> 4);
        int xq = it & 15;
        int r0 = 4 * y - 2;
        const float4* t4 = ((const float4*)tmp) + xq;
        float4 acc;
        if (r0 >= 0 && r0 + 8 <= PS) {
            const float4* tp = t4 + (size_t)(r0 - rb) * 16;
            acc = make_float4(0.f, 0.f, 0.f, 0.f);
            acc = f4fma(W0, tp[0*16], acc);
            acc = f4fma(W1, tp[1*16], acc);
            acc = f4fma(W2, tp[2*16], acc);
            acc = f4fma(W3, tp[3*16], acc);
            acc = f4fma(W4, tp[4*16], acc);
            acc = f4fma(W5, tp[5*16], acc);
            acc = f4fma(W6, tp[6*16], acc);
            acc = f4fma(W7, tp[7*16], acc);
        } else {
            acc = make_float4(0.f, 0.f, 0.f, 0.f);
            float wsum = 0.f;
#pragma unroll
            for (int k = 0; k < 8; k++) {
                int rr = r0 + k;
                if ((unsigned)rr < (unsigned)PS) {
                    acc = f4fma(W[k], t4[(size_t)(rr - rb) * 16], acc);
                    wsum += W[k];
                }
            }
            float inv = 1.0f / wsum;
            acc.x *= inv; acc.y *= inv; acc.z *= inv; acc.w *= inv;
        }
        ((float4*)(o + y * G))[xq] = acc;
    }
}

// ---------------- S = 2 slice ----------------
template <int ROWS>
__device__ void ds2_slice(const float* __restrict__ img, float* __restrict__ o,
                          int by, int bx, int y0, float* __restrict__ tmp) {
    constexpr int PS = 128, LR = 2 * ROWS + 2;
    constexpr float W0=0.125f, W1=0.375f, W2=0.375f, W3=0.125f;
    const float W[4] = {W0,W1,W2,W3};
    const int tid = threadIdx.x;
    const int rb  = 2 * y0 - 1;

    // ---- phase 1: horizontal. 8 threads/row, 8 outputs each ----
    for (int it = tid; it < LR * 8; it += NTHREADS) {
        int lr = it >> 3, q = it & 7;
        int r  = rb + lr;
        if ((unsigned)r >= (unsigned)PS) continue;
        int gy = by + r;
        float* drow = tmp + lr * G;
        int i0 = 8 * q;
        if ((unsigned)gy >= IMGSZ) {
#pragma unroll
            for (int k = 0; k < 8; k++) drow[i0 + k] = 0.f;
            continue;
        }
        const float* rowp = img + gy * IMGSZ;
        int istart = (q == 0) ? 1 : ((q == 7) ? 56 : i0);
        int g0 = bx + 2 * istart - 1;
        int base = g0 & ~3;
        int off  = g0 & 3;
        if (g0 >= 0 && base + 24 <= IMGSZ) {
            const float4* p = (const float4*)(rowp + base);
            float* dst = drow + istart;
            if (q == 0) {
                RUN_SWITCH(run2, 8, p, dst, off);        // outputs 1..7
                drow[0] = scalar_out<2>(rowp, bx, 0);
            } else if (q == 7) {
                RUN_SWITCH(run2, 8, p, dst, off);        // outputs 56..62
                drow[63] = scalar_out<2>(rowp, bx, 63);
            } else {
                RUN_SWITCH(run2, 9, p, dst, off);        // outputs i0..i0+7
            }
        } else {
#pragma unroll
            for (int k = 0; k < 8; k++) drow[i0 + k] = scalar_out<2>(rowp, bx, i0 + k);
        }
    }
    __syncthreads();

    // ---- phase 2: vertical, float4 per thread ----
    for (int it = tid; it < ROWS * 16; it += NTHREADS) {
        int y  = y0 + (it >> 4);
        int xq = it & 15;
        int r0 = 2 * y - 1;
        const float4* t4 = ((const float4*)tmp) + xq;
        float4 acc;
        if (r0 >= 0 && r0 + 4 <= PS) {
            const float4* tp = t4 + (size_t)(r0 - rb) * 16;
            acc = make_float4(0.f, 0.f, 0.f, 0.f);
            acc = f4fma(W0, tp[0*16], acc);
            acc = f4fma(W1, tp[1*16], acc);
            acc = f4fma(W2, tp[2*16], acc);
            acc = f4fma(W3, tp[3*16], acc);
        } else {
            acc = make_float4(0.f, 0.f, 0.f, 0.f);
            float wsum = 0.f;
#pragma unroll
            for (int k = 0; k < 4; k++) {
                int rr = r0 + k;
                if ((unsigned)rr < (unsigned)PS) {
                    acc = f4fma(W[k], t4[(size_t)(rr - rb) * 16], acc);
                    wsum += W[k];
                }
            }
            float inv = 1.0f / wsum;
            acc.x *= inv; acc.y *= inv; acc.z *= inv; acc.w *= inv;
        }
        ((float4*)(o + y * G))[xq] = acc;
    }
}

// Grid (1344 blocks), heavy work first:
//   [0, 768)     : S=4, 4 slices x 16 rows per (b,c)
//   [768, 1152)  : S=2, 2 slices x 32 rows per (b,c)
//   [1152, 1344) : direct 64x64 zero-padded crop of img0
__global__ __launch_bounds__(NTHREADS, 7)
void glimpse_kernel(const float* __restrict__ img0,
                    const float* __restrict__ img2,
                    const float* __restrict__ img4,
                    const float* __restrict__ loc,
                    float* __restrict__ out) {
    extern __shared__ float tmp[];

    int blk = blockIdx.x;
    int sel, bc, slice;
    if (blk < 768)       { sel = 0; bc = blk >> 2;          slice = blk & 3; }
    else if (blk < 1152) { sel = 1; bc = (blk - 768) >> 1;  slice = (blk - 768) & 1; }
    else                 { sel = 2; bc = blk - 1152;        slice = 0; }
    int b = bc / 3;
    int c = bc - b * 3;

    float lx = loc[2 * b + 0];
    float ly = loc[2 * b + 1];
    int sx = (int)(0.5f * ((lx + 1.0f) * 511.0f));
    int sy = (int)(0.5f * ((ly + 1.0f) * 511.0f));

    if (sel == 0) {
        const float* img = img4 + (size_t)(b * 3 + c) * IMGSZ * IMGSZ;
        float* o = out + (size_t)((b * 3 + 2) * 3 + c) * G * G;
        ds4_slice<16>(img, o, sy - 128, sx - 128, slice * 16, tmp);
    } else if (sel == 1) {
        const float* img = img2 + (size_t)(b * 3 + c) * IMGSZ * IMGSZ;
        float* o = out + (size_t)((b * 3 + 1) * 3 + c) * G * G;
        ds2_slice<32>(img, o, sy - 64, sx - 64, slice * 32, tmp);
    } else {
        const float* img = img0 + (size_t)(b * 3 + c) * IMGSZ * IMGSZ;
        float* o = out + (size_t)((b * 3 + 0) * 3 + c) * G * G;
        int by = sy - G / 2, bx = sx - G / 2;
        for (int idx = threadIdx.x; idx < G * G; idx += NTHREADS) {
            int y = idx >> 6, x = idx & 63;
            o[idx] = ldimg(img, by + y, bx + x);
        }
    }
}

extern "C" void kernel_launch(void* const* d_in, const int* in_sizes, int n_in,
                              void* d_out, int out_size) {
    const float* img0 = (const float*)d_in[0];
    const float* img2 = (const float*)d_in[1];
    const float* img4 = (const float*)d_in[2];
    const float* loc  = (const float*)d_in[3];
    float* out = (float*)d_out;

    const size_t smem = (size_t)68 * G * sizeof(float);  // 17408 B
    cudaFuncSetAttribute(glimpse_kernel,
                         cudaFuncAttributeMaxDynamicSharedMemorySize, (int)smem);
    glimpse_kernel<<<1344, NTHREADS, smem>>>(img0, img2, img4, loc, out);
}

// round 6
// speedup vs baseline: 2.3867x; 2.3867x over previous
#include <cuda_runtime.h>

#define G        64
#define IMGSZ    512
#define NTHREADS 256

#define EDGE_SCALE (1.0f / 0.875f)   // all patch-edge wsums are 28/32 = 7/8 = 0.875

__device__ __forceinline__ float ldimg(const float* __restrict__ img, int gy, int gx) {
    if ((unsigned)gy < IMGSZ && (unsigned)gx < IMGSZ)
        return __ldg(img + gy * IMGSZ + gx);
    return 0.0f;
}

// ======================= S = 4 (img4 -> window 2) =======================
// Vertical-first separable filter. Weights [1,3,5,7,7,5,3,1]/32.
// Chunk m = rows [4m-2, 4m+2): s_m = dot([1,3,5,7]/32), t_m = dot([7,5,3,1]/32),
// out_y = s_y + t_{y+1}. Rows outside patch/image load as 0; outputs y==0/63
// get *EDGE_SCALE (excluded-tap renorm, wsum=7/8).
// tmp layout: [ROWS][264] floats; column j stored at offset j+2, pads zeroed,
// so horizontal chunk i is the aligned float4 at index i (row = 66 float4s).
template <int ROWS>
__device__ void ds4_slice(const float* __restrict__ img, float* __restrict__ o,
                          int by, int bx, int y0, float* __restrict__ tmp) {
    constexpr int RP = 264;
    const int tid = threadIdx.x;

    if (tid < ROWS) {                 // zero the 4 pad cells of each row
        float* rp = tmp + tid * RP;
        rp[0] = 0.f; rp[1] = 0.f; rp[258] = 0.f; rp[259] = 0.f;
    }

    // ---- phase 1: vertical, one thread per patch column (256 columns) ----
    {
        const int j  = tid;
        const int gx = bx + j;
        if ((unsigned)gx >= (unsigned)IMGSZ) {
#pragma unroll
            for (int yy = 0; yy < ROWS; yy++) tmp[yy * RP + 2 + j] = 0.f;
        } else {
            const float* colp = img + gx;
            const int rlo = 4 * y0 - 2;
            const int rhi = 4 * (y0 + ROWS) + 1;
            const bool allok = (rlo >= 0) && (rhi < 256) &&
                               (by + rlo >= 0) && (by + rhi < IMGSZ);
            float sp = 0.f;
            if (allok) {
                const float* p = colp + (size_t)(by + rlo) * IMGSZ;
#pragma unroll 4
                for (int cm = 0; cm <= ROWS; cm++) {
                    float v0 = __ldg(p);
                    float v1 = __ldg(p + IMGSZ);
                    float v2 = __ldg(p + 2 * IMGSZ);
                    float v3 = __ldg(p + 3 * IMGSZ);
                    p += 4 * IMGSZ;
                    float s = fmaf(7.f/32, v3, fmaf(5.f/32, v2, fmaf(3.f/32, v1, (1.f/32)*v0)));
                    float t = fmaf(1.f/32, v3, fmaf(3.f/32, v2, fmaf(5.f/32, v1, (7.f/32)*v0)));
                    if (cm > 0) {
                        int y = y0 + cm - 1;
                        float raw = sp + t;
                        if (y == 0 || y == 63) raw *= EDGE_SCALE;
                        tmp[(cm - 1) * RP + 2 + j] = raw;
                    }
                    sp = s;
                }
            } else {
#pragma unroll 1
                for (int cm = 0; cm <= ROWS; cm++) {
                    int rbase = 4 * (y0 + cm) - 2;
                    float v[4];
#pragma unroll
                    for (int k = 0; k < 4; k++) {
                        int r  = rbase + k;
                        int gy = by + r;
                        v[k] = ((unsigned)r < 256u && (unsigned)gy < (unsigned)IMGSZ)
                               ? __ldg(colp + (size_t)gy * IMGSZ) : 0.f;
                    }
                    float s = fmaf(7.f/32, v[3], fmaf(5.f/32, v[2], fmaf(3.f/32, v[1], (1.f/32)*v[0])));
                    float t = fmaf(1.f/32, v[3], fmaf(3.f/32, v[2], fmaf(5.f/32, v[1], (7.f/32)*v[0])));
                    if (cm > 0) {
                        int y = y0 + cm - 1;
                        float raw = sp + t;
                        if (y == 0 || y == 63) raw *= EDGE_SCALE;
                        tmp[(cm - 1) * RP + 2 + j] = raw;
                    }
                    sp = s;
                }
            }
        }
    }
    __syncthreads();

    // ---- phase 2: horizontal from smem, aligned float4 chunks ----
    const float4* t4 = (const float4*)tmp;   // row stride 66 float4s
    for (int idx = tid; idx < ROWS * G; idx += NTHREADS) {
        int yy = idx >> 6, i = idx & 63;
        float4 a = t4[yy * 66 + i];
        float4 b = t4[yy * 66 + i + 1];
        float acc = (1.f/32)*a.x + (3.f/32)*a.y + (5.f/32)*a.z + (7.f/32)*a.w
                  + (7.f/32)*b.x + (5.f/32)*b.y + (3.f/32)*b.z + (1.f/32)*b.w;
        if (i == 0 || i == 63) acc *= EDGE_SCALE;
        o[(y0 + yy) * G + i] = acc;
    }
}

// ======================= S = 2 (img2 -> window 1) =======================
// Weights [1,3,3,1]/8. Chunk m = rows {2m-1, 2m}: s=[1,3]/8, t=[3,1]/8.
// 32 output rows per slice; threads split: j = tid&127 (column), h = tid>>7
// (half: 16 output rows each). tmp: [32][132], col j at offset j+1, pads 0,
// so horizontal chunk i is the aligned float2 at index i (row = 66 float2s).
__device__ void ds2_slice(const float* __restrict__ img, float* __restrict__ o,
                          int by, int bx, int y0, float* __restrict__ tmp) {
    constexpr int RP = 132;
    const int tid = threadIdx.x;

    if (tid < 32) {                  // zero pad cells
        float* rp = tmp + tid * RP;
        rp[0] = 0.f; rp[129] = 0.f;
    }

    // ---- phase 1: vertical ----
    {
        const int j   = tid & 127;
        const int h   = tid >> 7;
        const int ylo = y0 + 16 * h;          // global output row base for this half
        const int gx  = bx + j;
        if ((unsigned)gx >= (unsigned)IMGSZ) {
#pragma unroll
            for (int yy = 0; yy < 16; yy++) tmp[(16 * h + yy) * RP + 1 + j] = 0.f;
        } else {
            const float* colp = img + gx;
            const int rlo = 2 * ylo - 1;
            const int rhi = 2 * (ylo + 16);
            const bool allok = (rlo >= 0) && (rhi < 128) &&
                               (by + rlo >= 0) && (by + rhi < IMGSZ);
            float sp = 0.f;
            if (allok) {
                const float* p = colp + (size_t)(by + rlo) * IMGSZ;
#pragma unroll 4
                for (int cm = 0; cm <= 16; cm++) {
                    float v0 = __ldg(p);
                    float v1 = __ldg(p + IMGSZ);
                    p += 2 * IMGSZ;
                    float s = fmaf(3.f/8, v1, (1.f/8)*v0);
                    float t = fmaf(1.f/8, v1, (3.f/8)*v0);
                    if (cm > 0) {
                        int y = ylo + cm - 1;
                        float raw = sp + t;
                        if (y == 0 || y == 63) raw *= EDGE_SCALE;
                        tmp[(16 * h + cm - 1) * RP + 1 + j] = raw;
                    }
                    sp = s;
                }
            } else {
#pragma unroll 1
                for (int cm = 0; cm <= 16; cm++) {
                    int rbase = 2 * (ylo + cm) - 1;
                    float v[2];
#pragma unroll
                    for (int k = 0; k < 2; k++) {
                        int r  = rbase + k;
                        int gy = by + r;
                        v[k] = ((unsigned)r < 128u && (unsigned)gy < (unsigned)IMGSZ)
                               ? __ldg(colp + (size_t)gy * IMGSZ) : 0.f;
                    }
                    float s = fmaf(3.f/8, v[1], (1.f/8)*v[0]);
                    float t = fmaf(1.f/8, v[1], (3.f/8)*v[0]);
                    if (cm > 0) {
                        int y = ylo + cm - 1;
                        float raw = sp + t;
                        if (y == 0 || y == 63) raw *= EDGE_SCALE;
                        tmp[(16 * h + cm - 1) * RP + 1 + j] = raw;
                    }
                    sp = s;
                }
            }
        }
    }
    __syncthreads();

    // ---- phase 2: horizontal from smem, aligned float2 chunks ----
    const float2* t2 = (const float2*)tmp;   // row stride 66 float2s
    for (int idx = tid; idx < 32 * G; idx += NTHREADS) {
        int yy = idx >> 6, i = idx & 63;
        float2 a = t2[yy * 66 + i];
        float2 b = t2[yy * 66 + i + 1];
        float acc = (1.f/8)*a.x + (3.f/8)*a.y + (3.f/8)*b.x + (1.f/8)*b.y;
        if (i == 0 || i == 63) acc *= EDGE_SCALE;
        o[(y0 + yy) * G + i] = acc;
    }
}

// Grid (1344 blocks), heavy work first:
//   [0, 768)     : S=4, 4 slices x 16 rows per (b,c)
//   [768, 1152)  : S=2, 2 slices x 32 rows per (b,c)
//   [1152, 1344) : direct 64x64 zero-padded crop of img0
__global__ __launch_bounds__(NTHREADS, 6)
void glimpse_kernel(const float* __restrict__ img0,
                    const float* __restrict__ img2,
                    const float* __restrict__ img4,
                    const float* __restrict__ loc,
                    float* __restrict__ out) {
    extern __shared__ float tmp[];

    int blk = blockIdx.x;
    int sel, bc, slice;
    if (blk < 768)       { sel = 0; bc = blk >> 2;          slice = blk & 3; }
    else if (blk < 1152) { sel = 1; bc = (blk - 768) >> 1;  slice = (blk - 768) & 1; }
    else                 { sel = 2; bc = blk - 1152;        slice = 0; }
    int b = bc / 3;
    int c = bc - b * 3;

    // start index, matching jnp: trunc(0.5f * ((loc + 1.0f) * 511.0f))
    float lx = loc[2 * b + 0];
    float ly = loc[2 * b + 1];
    int sx = (int)(0.5f * ((lx + 1.0f) * 511.0f));
    int sy = (int)(0.5f * ((ly + 1.0f) * 511.0f));

    if (sel == 0) {
        const float* img = img4 + (size_t)(b * 3 + c) * IMGSZ * IMGSZ;
        float* o = out + (size_t)((b * 3 + 2) * 3 + c) * G * G;
        ds4_slice<16>(img, o, sy - 128, sx - 128, slice * 16, tmp);
    } else if (sel == 1) {
        const float* img = img2 + (size_t)(b * 3 + c) * IMGSZ * IMGSZ;
        float* o = out + (size_t)((b * 3 + 1) * 3 + c) * G * G;
        ds2_slice(img, o, sy - 64, sx - 64, slice * 32, tmp);
    } else {
        const float* img = img0 + (size_t)(b * 3 + c) * IMGSZ * IMGSZ;
        float* o = out + (size_t)((b * 3 + 0) * 3 + c) * G * G;
        int by = sy - G / 2, bx = sx - G / 2;
        for (int idx = threadIdx.x; idx < G * G; idx += NTHREADS) {
            int y = idx >> 6, x = idx & 63;
            o[idx] = ldimg(img, by + y, bx + x);
        }
    }
}

extern "C" void kernel_launch(void* const* d_in, const int* in_sizes, int n_in,
                              void* d_out, int out_size) {
    const float* img0 = (const float*)d_in[0];
    const float* img2 = (const float*)d_in[1];
    const float* img4 = (const float*)d_in[2];
    const float* loc  = (const float*)d_in[3];
    float* out = (float*)d_out;

    const size_t smem = 16896;   // max(16*264, 32*132) * 4 bytes
    cudaFuncSetAttribute(glimpse_kernel,
                         cudaFuncAttributeMaxDynamicSharedMemorySize, (int)smem);
    glimpse_kernel<<<1344, NTHREADS, smem>>>(img0, img2, img4, loc, out);
}

// round 7
// speedup vs baseline: 3.0862x; 1.2931x over previous
#include <cuda_runtime.h>

#define G        64
#define IMGSZ    512
#define NTHREADS 512

#define EDGE_SCALE (1.0f / 0.875f)   // all patch-edge wsums are 7/8

__device__ __forceinline__ float ldimg(const float* __restrict__ img, int gy, int gx) {
    if ((unsigned)gy < IMGSZ && (unsigned)gx < IMGSZ)
        return __ldg(img + gy * IMGSZ + gx);
    return 0.0f;
}

// ======================= S = 4 (img4 -> window 2) =======================
// Vertical-first separable filter. Weights [1,3,5,7,7,5,3,1]/32.
// Chunk m = rows [4m-2, 4m+2): s_m = dot([1,3,5,7]/32), t_m = dot([7,5,3,1]/32),
// out_y = s_y + t_{y+1}. Rows outside patch/image load as 0; outputs y==0/63
// get *EDGE_SCALE (excluded-tap renorm).
// 512 threads: j = tid&255 (patch column), h = tid>>8 (row half, 8 outputs).
// tmp layout: [16][264]; column j at offset j+2, pads zeroed, so horizontal
// chunk i is the aligned float4 at index i (row = 66 float4s).
__device__ void ds4_slice(const float* __restrict__ img, float* __restrict__ o,
                          int by, int bx, int y0, float* __restrict__ tmp) {
    constexpr int RP = 264;
    const int tid = threadIdx.x;

    if (tid < 16) {                 // zero the 4 pad cells of each row
        float* rp = tmp + tid * RP;
        rp[0] = 0.f; rp[1] = 0.f; rp[258] = 0.f; rp[259] = 0.f;
    }

    // ---- phase 1: vertical; 2 threads per column, 8 output rows each ----
    {
        const int j   = tid & 255;
        const int h   = tid >> 8;          // 0..1
        const int ylo = y0 + 8 * h;
        const int gx  = bx + j;
        if ((unsigned)gx >= (unsigned)IMGSZ) {
#pragma unroll
            for (int yy = 0; yy < 8; yy++) tmp[(8 * h + yy) * RP + 2 + j] = 0.f;
        } else {
            const float* colp = img + gx;
            const int rlo = 4 * ylo - 2;
            const int rhi = 4 * (ylo + 8) + 1;
            const bool allok = (rlo >= 0) && (rhi < 256) &&
                               (by + rlo >= 0) && (by + rhi < IMGSZ);
            float sp = 0.f;
            if (allok) {
                const float* p = colp + (size_t)(by + rlo) * IMGSZ;
#pragma unroll 3
                for (int cm = 0; cm <= 8; cm++) {
                    float v0 = __ldg(p);
                    float v1 = __ldg(p + IMGSZ);
                    float v2 = __ldg(p + 2 * IMGSZ);
                    float v3 = __ldg(p + 3 * IMGSZ);
                    p += 4 * IMGSZ;
                    float s = fmaf(7.f/32, v3, fmaf(5.f/32, v2, fmaf(3.f/32, v1, (1.f/32)*v0)));
                    float t = fmaf(1.f/32, v3, fmaf(3.f/32, v2, fmaf(5.f/32, v1, (7.f/32)*v0)));
                    if (cm > 0) {
                        int y = ylo + cm - 1;
                        float raw = sp + t;
                        if (y == 0 || y == 63) raw *= EDGE_SCALE;
                        tmp[(8 * h + cm - 1) * RP + 2 + j] = raw;
                    }
                    sp = s;
                }
            } else {
#pragma unroll 1
                for (int cm = 0; cm <= 8; cm++) {
                    int rbase = 4 * (ylo + cm) - 2;
                    float v[4];
#pragma unroll
                    for (int k = 0; k < 4; k++) {
                        int r  = rbase + k;
                        int gy = by + r;
                        v[k] = ((unsigned)r < 256u && (unsigned)gy < (unsigned)IMGSZ)
                               ? __ldg(colp + (size_t)gy * IMGSZ) : 0.f;
                    }
                    float s = fmaf(7.f/32, v[3], fmaf(5.f/32, v[2], fmaf(3.f/32, v[1], (1.f/32)*v[0])));
                    float t = fmaf(1.f/32, v[3], fmaf(3.f/32, v[2], fmaf(5.f/32, v[1], (7.f/32)*v[0])));
                    if (cm > 0) {
                        int y = ylo + cm - 1;
                        float raw = sp + t;
                        if (y == 0 || y == 63) raw *= EDGE_SCALE;
                        tmp[(8 * h + cm - 1) * RP + 2 + j] = raw;
                    }
                    sp = s;
                }
            }
        }
    }
    __syncthreads();

    // ---- phase 2: horizontal from smem, aligned float4 chunks ----
    const float4* t4 = (const float4*)tmp;   // row stride 66 float4s
    for (int idx = tid; idx < 16 * G; idx += NTHREADS) {
        int yy = idx >> 6, i = idx & 63;
        float4 a = t4[yy * 66 + i];
        float4 b = t4[yy * 66 + i + 1];
        float acc = (1.f/32)*a.x + (3.f/32)*a.y + (5.f/32)*a.z + (7.f/32)*a.w
                  + (7.f/32)*b.x + (5.f/32)*b.y + (3.f/32)*b.z + (1.f/32)*b.w;
        if (i == 0 || i == 63) acc *= EDGE_SCALE;
        o[(y0 + yy) * G + i] = acc;
    }
}

// ======================= S = 2 (img2 -> window 1) =======================
// Weights [1,3,3,1]/8. Chunk m = rows {2m-1, 2m}: s=[1,3]/8, t=[3,1]/8.
// 32 output rows per slice; 512 threads: j = tid&127 (column), h = tid>>7
// (quarter: 8 output rows each). tmp: [32][132], col j at offset j+1, pads 0,
// so horizontal chunk i is the aligned float2 at index i (row = 66 float2s).
__device__ void ds2_slice(const float* __restrict__ img, float* __restrict__ o,
                          int by, int bx, int y0, float* __restrict__ tmp) {
    constexpr int RP = 132;
    const int tid = threadIdx.x;

    if (tid < 32) {                  // zero pad cells
        float* rp = tmp + tid * RP;
        rp[0] = 0.f; rp[129] = 0.f;
    }

    // ---- phase 1: vertical; 4 threads per column, 8 output rows each ----
    {
        const int j   = tid & 127;
        const int h   = tid >> 7;            // 0..3
        const int ylo = y0 + 8 * h;
        const int gx  = bx + j;
        if ((unsigned)gx >= (unsigned)IMGSZ) {
#pragma unroll
            for (int yy = 0; yy < 8; yy++) tmp[(8 * h + yy) * RP + 1 + j] = 0.f;
        } else {
            const float* colp = img + gx;
            const int rlo = 2 * ylo - 1;
            const int rhi = 2 * (ylo + 8);
            const bool allok = (rlo >= 0) && (rhi < 128) &&
                               (by + rlo >= 0) && (by + rhi < IMGSZ);
            float sp = 0.f;
            if (allok) {
                const float* p = colp + (size_t)(by + rlo) * IMGSZ;
#pragma unroll 3
                for (int cm = 0; cm <= 8; cm++) {
                    float v0 = __ldg(p);
                    float v1 = __ldg(p + IMGSZ);
                    p += 2 * IMGSZ;
                    float s = fmaf(3.f/8, v1, (1.f/8)*v0);
                    float t = fmaf(1.f/8, v1, (3.f/8)*v0);
                    if (cm > 0) {
                        int y = ylo + cm - 1;
                        float raw = sp + t;
                        if (y == 0 || y == 63) raw *= EDGE_SCALE;
                        tmp[(8 * h + cm - 1) * RP + 1 + j] = raw;
                    }
                    sp = s;
                }
            } else {
#pragma unroll 1
                for (int cm = 0; cm <= 8; cm++) {
                    int rbase = 2 * (ylo + cm) - 1;
                    float v[2];
#pragma unroll
                    for (int k = 0; k < 2; k++) {
                        int r  = rbase + k;
                        int gy = by + r;
                        v[k] = ((unsigned)r < 128u && (unsigned)gy < (unsigned)IMGSZ)
                               ? __ldg(colp + (size_t)gy * IMGSZ) : 0.f;
                    }
                    float s = fmaf(3.f/8, v[1], (1.f/8)*v[0]);
                    float t = fmaf(1.f/8, v[1], (3.f/8)*v[0]);
                    if (cm > 0) {
                        int y = ylo + cm - 1;
                        float raw = sp + t;
                        if (y == 0 || y == 63) raw *= EDGE_SCALE;
                        tmp[(8 * h + cm - 1) * RP + 1 + j] = raw;
                    }
                    sp = s;
                }
            }
        }
    }
    __syncthreads();

    // ---- phase 2: horizontal from smem, aligned float2 chunks ----
    const float2* t2 = (const float2*)tmp;   // row stride 66 float2s
    for (int idx = tid; idx < 32 * G; idx += NTHREADS) {
        int yy = idx >> 6, i = idx & 63;
        float2 a = t2[yy * 66 + i];
        float2 b = t2[yy * 66 + i + 1];
        float acc = (1.f/8)*a.x + (3.f/8)*a.y + (3.f/8)*b.x + (1.f/8)*b.y;
        if (i == 0 || i == 63) acc *= EDGE_SCALE;
        o[(y0 + yy) * G + i] = acc;
    }
}

// Grid (1344 blocks), heavy work first:
//   [0, 768)     : S=4, 4 slices x 16 rows per (b,c)
//   [768, 1152)  : S=2, 2 slices x 32 rows per (b,c)
//   [1152, 1344) : direct 64x64 zero-padded crop of img0
__global__ __launch_bounds__(NTHREADS, 4)
void glimpse_kernel(const float* __restrict__ img0,
                    const float* __restrict__ img2,
                    const float* __restrict__ img4,
                    const float* __restrict__ loc,
                    float* __restrict__ out) {
    extern __shared__ float tmp[];

    int blk = blockIdx.x;
    int sel, bc, slice;
    if (blk < 768)       { sel = 0; bc = blk >> 2;          slice = blk & 3; }
    else if (blk < 1152) { sel = 1; bc = (blk - 768) >> 1;  slice = (blk - 768) & 1; }
    else                 { sel = 2; bc = blk - 1152;        slice = 0; }
    int b = bc / 3;
    int c = bc - b * 3;

    // start index, matching jnp: trunc(0.5f * ((loc + 1.0f) * 511.0f))
    float lx = loc[2 * b + 0];
    float ly = loc[2 * b + 1];
    int sx = (int)(0.5f * ((lx + 1.0f) * 511.0f));
    int sy = (int)(0.5f * ((ly + 1.0f) * 511.0f));

    if (sel == 0) {
        const float* img = img4 + (size_t)(b * 3 + c) * IMGSZ * IMGSZ;
        float* o = out + (size_t)((b * 3 + 2) * 3 + c) * G * G;
        ds4_slice(img, o, sy - 128, sx - 128, slice * 16, tmp);
    } else if (sel == 1) {
        const float* img = img2 + (size_t)(b * 3 + c) * IMGSZ * IMGSZ;
        float* o = out + (size_t)((b * 3 + 1) * 3 + c) * G * G;
        ds2_slice(img, o, sy - 64, sx - 64, slice * 32, tmp);
    } else {
        const float* img = img0 + (size_t)(b * 3 + c) * IMGSZ * IMGSZ;
        float* o = out + (size_t)((b * 3 + 0) * 3 + c) * G * G;
        int by = sy - G / 2, bx = sx - G / 2;
        for (int idx = threadIdx.x; idx < G * G; idx += NTHREADS) {
            int y = idx >> 6, x = idx & 63;
            o[idx] = ldimg(img, by + y, bx + x);
        }
    }
}

extern "C" void kernel_launch(void* const* d_in, const int* in_sizes, int n_in,
                              void* d_out, int out_size) {
    const float* img0 = (const float*)d_in[0];
    const float* img2 = (const float*)d_in[1];
    const float* img4 = (const float*)d_in[2];
    const float* loc  = (const float*)d_in[3];
    float* out = (float*)d_out;

    const size_t smem = 16896;   // max(16*264, 32*132) * 4 bytes
    cudaFuncSetAttribute(glimpse_kernel,
                         cudaFuncAttributeMaxDynamicSharedMemorySize, (int)smem);
    glimpse_kernel<<<1344, NTHREADS, smem>>>(img0, img2, img4, loc, out);
}